// round 1
// baseline (speedup 1.0000x reference)
#include <cuda_runtime.h>
#include <cstdint>

#define B_ 4
#define C_ 64
#define N_ 40960
#define K_ 16
#define D_ 128
#define EPS_ 1e-5f

// Scratch: p[b][m][c] = relu(BN1(w1 @ f[b,:,m])), point-major rows of 64 floats (256B)
__device__ float g_p[(size_t)B_ * N_ * C_];
// Fused (BN-scaled) weights, stored transposed [c][o] for vectorized smem reads
__device__ float g_w1t[C_ * C_];
__device__ float g_w2t[C_ * D_];
__device__ float g_w3t[C_ * D_];
__device__ float g_sh1[C_];
__device__ float g_sh2[D_];
__device__ float g_sh3[D_];

// ---------- packed fp32x2 helpers (Blackwell 2x fp32 path) ----------
__device__ __forceinline__ unsigned long long pk2(float lo, float hi) {
    unsigned long long r;
    asm("mov.b64 %0, {%1, %2};" : "=l"(r) : "f"(lo), "f"(hi));
    return r;
}
__device__ __forceinline__ void upk2(unsigned long long v, float& lo, float& hi) {
    asm("mov.b64 {%0, %1}, %2;" : "=f"(lo), "=f"(hi) : "l"(v));
}
__device__ __forceinline__ unsigned long long ffma2(unsigned long long a, unsigned long long b,
                                                    unsigned long long c) {
    unsigned long long d;
    asm("fma.rn.f32x2 %0, %1, %2, %3;" : "=l"(d) : "l"(a), "l"(b), "l"(c));
    return d;
}
__device__ __forceinline__ unsigned long long fadd2(unsigned long long a, unsigned long long b) {
    unsigned long long d;
    asm("add.rn.f32x2 %0, %1, %2;" : "=l"(d) : "l"(a), "l"(b));
    return d;
}

// ---------- prep: fuse BN scale into weights, transpose to [c][o] ----------
__global__ void prep_kernel(const float* __restrict__ w1, const float* __restrict__ g1,
                            const float* __restrict__ b1, const float* __restrict__ m1,
                            const float* __restrict__ v1,
                            const float* __restrict__ w2, const float* __restrict__ g2,
                            const float* __restrict__ b2, const float* __restrict__ m2,
                            const float* __restrict__ v2,
                            const float* __restrict__ w3, const float* __restrict__ g3,
                            const float* __restrict__ b3, const float* __restrict__ m3,
                            const float* __restrict__ v3) {
    const int t = blockIdx.x * blockDim.x + threadIdx.x;
    const int stride = gridDim.x * blockDim.x;
    for (int i = t; i < C_ * C_; i += stride) {
        int o = i >> 6, c = i & 63;
        float sc = g1[o] / sqrtf(v1[o] + EPS_);
        g_w1t[c * C_ + o] = w1[o * C_ + c] * sc;
    }
    for (int i = t; i < D_ * C_; i += stride) {
        int o = i >> 6, c = i & 63;
        float sc2 = g2[o] / sqrtf(v2[o] + EPS_);
        g_w2t[c * D_ + o] = w2[o * C_ + c] * sc2;
        float sc3 = g3[o] / sqrtf(v3[o] + EPS_);
        g_w3t[c * D_ + o] = w3[o * C_ + c] * sc3;
    }
    if (t < C_) {
        float sc = g1[t] / sqrtf(v1[t] + EPS_);
        g_sh1[t] = b1[t] - m1[t] * sc;
    }
    if (t < D_) {
        float sc2 = g2[t] / sqrtf(v2[t] + EPS_);
        g_sh2[t] = b2[t] - m2[t] * sc2;
        float sc3 = g3[t] / sqrtf(v3[t] + EPS_);
        g_sh3[t] = b3[t] - m3[t] * sc3;
    }
}

// ---------- K1: p[b][m][:] = relu(w1s @ f[b,:,m] + sh1), tile = 256 points ----------
__global__ __launch_bounds__(256, 2) void k1_kernel(const float* __restrict__ f) {
    extern __shared__ float sm[];
    float* fsm = sm;                 // [64][256]   f tile, [c][j]
    float* wsm = sm + 64 * 256;      // [64][64]    w1t tile, [c][o]
    float* sh  = wsm + 64 * 64;      // [64]
    const int tid = threadIdx.x;
    const int b = blockIdx.y;
    const int n0 = blockIdx.x * 256;
    const float* fb = f + (size_t)b * C_ * N_ + n0;

    #pragma unroll
    for (int i = tid; i < 64 * 64; i += 256) {      // 4096 float4 of f tile
        int c = i >> 6, j4 = i & 63;
        ((float4*)(fsm + c * 256))[j4] = ((const float4*)(fb + (size_t)c * N_))[j4];
    }
    #pragma unroll
    for (int i = tid; i < 1024; i += 256)
        ((float4*)wsm)[i] = ((const float4*)g_w1t)[i];
    if (tid < 64) sh[tid] = g_sh1[tid];
    __syncthreads();

    const int jg = tid & 63, og = tid >> 6;
    const int j0 = jg * 4, o0 = og * 16;
    unsigned long long acc[4][8];
    #pragma unroll
    for (int l = 0; l < 4; ++l)
        #pragma unroll
        for (int m = 0; m < 8; ++m) acc[l][m] = 0ULL;

    #pragma unroll 4
    for (int c = 0; c < 64; ++c) {
        float4 fv = *(const float4*)(fsm + c * 256 + j0);
        unsigned long long fp[4];
        fp[0] = pk2(fv.x, fv.x); fp[1] = pk2(fv.y, fv.y);
        fp[2] = pk2(fv.z, fv.z); fp[3] = pk2(fv.w, fv.w);
        const ulonglong2* wp = (const ulonglong2*)(wsm + c * 64 + o0);
        ulonglong2 wA = wp[0], wB = wp[1], wC = wp[2], wD = wp[3];
        unsigned long long wv[8] = {wA.x, wA.y, wB.x, wB.y, wC.x, wC.y, wD.x, wD.y};
        #pragma unroll
        for (int l = 0; l < 4; ++l)
            #pragma unroll
            for (int m = 0; m < 8; ++m)
                acc[l][m] = ffma2(fp[l], wv[m], acc[l][m]);
    }

    float* pb = g_p + ((size_t)b * N_ + n0) * 64;
    #pragma unroll
    for (int l = 0; l < 4; ++l) {
        float o[16];
        #pragma unroll
        for (int m = 0; m < 8; ++m) upk2(acc[l][m], o[2 * m], o[2 * m + 1]);
        #pragma unroll
        for (int i = 0; i < 16; ++i) o[i] = fmaxf(o[i] + sh[o0 + i], 0.0f);
        float* dst = pb + (size_t)(j0 + l) * 64 + o0;
        *(float4*)(dst)      = make_float4(o[0],  o[1],  o[2],  o[3]);
        *(float4*)(dst + 4)  = make_float4(o[4],  o[5],  o[6],  o[7]);
        *(float4*)(dst + 8)  = make_float4(o[8],  o[9],  o[10], o[11]);
        *(float4*)(dst + 12) = make_float4(o[12], o[13], o[14], o[15]);
    }
}

// ---------- K2: gather-sum p + two 128x64 matvecs + residual, tile = 64 points ----------
__global__ __launch_bounds__(256, 2) void k2_kernel(const float* __restrict__ f,
                                                    const int* __restrict__ nidx,
                                                    float* __restrict__ out) {
    extern __shared__ float sm[];
    float* fsm  = sm;                // [64][64]  f tile, [c][j]
    float* hs   = sm + 4096;         // [64][64]  hsum,   [c][j]
    float* w2s  = sm + 8192;         // [64][128] w2t
    float* w3s  = w2s + 8192;        // [64][128] w3t
    float* sh2  = w3s + 8192;        // [128]
    float* sh3  = sh2 + 128;         // [128]
    int*   idxs = (int*)(sh3 + 128); // [64][16]

    const int tid = threadIdx.x;
    const int b = blockIdx.y;
    const int n0 = blockIdx.x * 64;
    const float* fb = f + (size_t)b * C_ * N_ + n0;

    #pragma unroll
    for (int i = tid; i < 1024; i += 256) {          // 1024 float4 of f tile
        int c = i >> 4, j4 = i & 15;
        ((float4*)(fsm + c * 64))[j4] = ((const float4*)(fb + (size_t)c * N_))[j4];
    }
    #pragma unroll
    for (int i = tid; i < 2048; i += 256) {
        ((float4*)w2s)[i] = ((const float4*)g_w2t)[i];
        ((float4*)w3s)[i] = ((const float4*)g_w3t)[i];
    }
    {
        const int* ib = nidx + ((size_t)b * N_ + n0) * 16;
        ((int4*)idxs)[tid] = ((const int4*)ib)[tid]; // 256 int4 = 1024 ints
    }
    if (tid < 128) { sh2[tid] = g_sh2[tid]; sh3[tid] = g_sh3[tid]; }
    __syncthreads();

    // --- gather-sum: thread (j = tid/4, 16 channels per q) ---
    {
        const int j = tid >> 2, c0 = (tid & 3) * 16;
        const float* pb = g_p + (size_t)b * N_ * 64 + c0;
        unsigned long long s[8];
        #pragma unroll
        for (int i = 0; i < 8; ++i) s[i] = 0ULL;
        #pragma unroll 4
        for (int k = 0; k < 16; ++k) {
            int mi = idxs[j * 16 + k];
            const ulonglong2* row = (const ulonglong2*)(pb + (size_t)mi * 64);
            ulonglong2 v0 = row[0], v1 = row[1], v2 = row[2], v3 = row[3];
            s[0] = fadd2(s[0], v0.x); s[1] = fadd2(s[1], v0.y);
            s[2] = fadd2(s[2], v1.x); s[3] = fadd2(s[3], v1.y);
            s[4] = fadd2(s[4], v2.x); s[5] = fadd2(s[5], v2.y);
            s[6] = fadd2(s[6], v3.x); s[7] = fadd2(s[7], v3.y);
        }
        float tv[16];
        #pragma unroll
        for (int i = 0; i < 8; ++i) upk2(s[i], tv[2 * i], tv[2 * i + 1]);
        #pragma unroll
        for (int i = 0; i < 16; ++i) hs[(c0 + i) * 64 + j] = tv[i];
    }
    __syncthreads();

    // --- matvec phase: thread = 4 points x 8 outputs x 2 matrices ---
    const int jg = tid & 15, og = tid >> 4;
    const int j0 = jg * 4, o0 = og * 8;
    unsigned long long ah[4][4], av[4][4];
    #pragma unroll
    for (int l = 0; l < 4; ++l)
        #pragma unroll
        for (int m = 0; m < 4; ++m) { ah[l][m] = 0ULL; av[l][m] = 0ULL; }

    #pragma unroll 4
    for (int c = 0; c < 64; ++c) {
        float4 hv = *(const float4*)(hs + c * 64 + j0);
        float4 fv = *(const float4*)(fsm + c * 64 + j0);
        unsigned long long hp[4], fp[4];
        hp[0] = pk2(hv.x, hv.x); hp[1] = pk2(hv.y, hv.y);
        hp[2] = pk2(hv.z, hv.z); hp[3] = pk2(hv.w, hv.w);
        fp[0] = pk2(fv.x, fv.x); fp[1] = pk2(fv.y, fv.y);
        fp[2] = pk2(fv.z, fv.z); fp[3] = pk2(fv.w, fv.w);
        ulonglong2 w2a = *(const ulonglong2*)(w2s + c * 128 + o0);
        ulonglong2 w2b = *(const ulonglong2*)(w2s + c * 128 + o0 + 4);
        ulonglong2 w3a = *(const ulonglong2*)(w3s + c * 128 + o0);
        ulonglong2 w3b = *(const ulonglong2*)(w3s + c * 128 + o0 + 4);
        unsigned long long w2v[4] = {w2a.x, w2a.y, w2b.x, w2b.y};
        unsigned long long w3v[4] = {w3a.x, w3a.y, w3b.x, w3b.y};
        #pragma unroll
        for (int l = 0; l < 4; ++l)
            #pragma unroll
            for (int m = 0; m < 4; ++m) {
                ah[l][m] = ffma2(hp[l], w2v[m], ah[l][m]);
                av[l][m] = ffma2(fp[l], w3v[m], av[l][m]);
            }
    }

    float res[4][8];
    #pragma unroll
    for (int l = 0; l < 4; ++l)
        #pragma unroll
        for (int m = 0; m < 4; ++m) {
            float hlo, hhi, slo, shi;
            upk2(ah[l][m], hlo, hhi);
            upk2(av[l][m], slo, shi);
            int oo = o0 + 2 * m;
            res[l][2 * m]     = fmaxf(hlo + sh2[oo], 0.0f)     + fmaxf(slo + sh3[oo], 0.0f);
            res[l][2 * m + 1] = fmaxf(hhi + sh2[oo + 1], 0.0f) + fmaxf(shi + sh3[oo + 1], 0.0f);
        }

    float* ob = out + (size_t)b * D_ * N_ + n0;
    #pragma unroll
    for (int o = 0; o < 8; ++o) {
        *(float4*)(ob + (size_t)(o0 + o) * N_ + j0) =
            make_float4(res[0][o], res[1][o], res[2][o], res[3][o]);
    }
}

extern "C" void kernel_launch(void* const* d_in, const int* in_sizes, int n_in,
                              void* d_out, int out_size) {
    const float* feature = (const float*)d_in[0];
    const int*   nidx    = (const int*)d_in[1];
    const float* w1 = (const float*)d_in[2];
    const float* g1 = (const float*)d_in[3];
    const float* b1 = (const float*)d_in[4];
    const float* m1 = (const float*)d_in[5];
    const float* v1 = (const float*)d_in[6];
    const float* w2 = (const float*)d_in[7];
    const float* g2 = (const float*)d_in[8];
    const float* b2 = (const float*)d_in[9];
    const float* m2 = (const float*)d_in[10];
    const float* v2 = (const float*)d_in[11];
    const float* w3 = (const float*)d_in[12];
    const float* g3 = (const float*)d_in[13];
    const float* b3 = (const float*)d_in[14];
    const float* m3 = (const float*)d_in[15];
    const float* v3 = (const float*)d_in[16];
    float* out = (float*)d_out;

    const int SM1 = (64 * 256 + 64 * 64 + 64) * 4;                       // 82176
    const int SM2 = (4096 + 4096 + 8192 + 8192 + 256) * 4 + 1024 * 4;    // 103424
    cudaFuncSetAttribute(k1_kernel, cudaFuncAttributeMaxDynamicSharedMemorySize, SM1);
    cudaFuncSetAttribute(k2_kernel, cudaFuncAttributeMaxDynamicSharedMemorySize, SM2);

    prep_kernel<<<32, 256>>>(w1, g1, b1, m1, v1, w2, g2, b2, m2, v2, w3, g3, b3, m3, v3);
    k1_kernel<<<dim3(N_ / 256, B_), 256, SM1>>>(feature);
    k2_kernel<<<dim3(N_ / 64, B_), 256, SM2>>>(feature, nidx, out);
}

// round 3
// speedup vs baseline: 1.3154x; 1.3154x over previous
#include <cuda_runtime.h>
#include <cuda_bf16.h>
#include <cuda_fp16.h>
#include <cstdint>

#define B_ 4
#define C_ 64
#define N_ 40960
#define K_ 16
#define D_ 128
#define EPS_ 1e-5f
#define NT_ 256
#define TILES_ 640   // B_ * N_/NT_

// ---------------- global scratch ----------------
__device__ __half g_p[(size_t)B_ * N_ * C_];   // relu(BN1(w1@f)) per point, fp16 128B rows
__device__ float g_w1t[C_ * C_];               // fused w1 transposed [c][o] fp32 (K1)
__device__ __nv_bfloat16 g_w2hi[D_ * C_], g_w2lo[D_ * C_];  // fused w2 split, [o][c]
__device__ __nv_bfloat16 g_w3hi[D_ * C_], g_w3lo[D_ * C_];
__device__ float g_sh1[C_], g_sh2[D_], g_sh3[D_];
__device__ int g_ticket;

// ---------------- helpers ----------------
__device__ __forceinline__ void mma16816(float* d, const uint32_t* a, const uint32_t* b) {
    asm volatile(
        "mma.sync.aligned.m16n8k16.row.col.f32.bf16.bf16.f32 "
        "{%0,%1,%2,%3}, {%4,%5,%6,%7}, {%8,%9}, {%0,%1,%2,%3};\n"
        : "+f"(d[0]), "+f"(d[1]), "+f"(d[2]), "+f"(d[3])
        : "r"(a[0]), "r"(a[1]), "r"(a[2]), "r"(a[3]), "r"(b[0]), "r"(b[1]));
}

__device__ __forceinline__ void split2(float x0, float x1, uint32_t& hi, uint32_t& lo) {
    __nv_bfloat16 h0 = __float2bfloat16(x0);
    __nv_bfloat16 h1 = __float2bfloat16(x1);
    __nv_bfloat16 l0 = __float2bfloat16(x0 - __bfloat162float(h0));
    __nv_bfloat16 l1 = __float2bfloat16(x1 - __bfloat162float(h1));
    __nv_bfloat162 hh = __halves2bfloat162(h0, h1);
    __nv_bfloat162 ll = __halves2bfloat162(l0, l1);
    hi = *(uint32_t*)&hh;
    lo = *(uint32_t*)&ll;
}

// ---------- packed fp32x2 helpers (K1) ----------
__device__ __forceinline__ unsigned long long pk2(float lo, float hi) {
    unsigned long long r;
    asm("mov.b64 %0, {%1, %2};" : "=l"(r) : "f"(lo), "f"(hi));
    return r;
}
__device__ __forceinline__ void upk2(unsigned long long v, float& lo, float& hi) {
    asm("mov.b64 {%0, %1}, %2;" : "=f"(lo), "=f"(hi) : "l"(v));
}
__device__ __forceinline__ unsigned long long ffma2(unsigned long long a, unsigned long long b,
                                                    unsigned long long c) {
    unsigned long long d;
    asm("fma.rn.f32x2 %0, %1, %2, %3;" : "=l"(d) : "l"(a), "l"(b), "l"(c));
    return d;
}

// ---------------- prep ----------------
__global__ void prep_kernel(const float* __restrict__ w1, const float* __restrict__ g1,
                            const float* __restrict__ b1, const float* __restrict__ m1,
                            const float* __restrict__ v1,
                            const float* __restrict__ w2, const float* __restrict__ g2,
                            const float* __restrict__ b2, const float* __restrict__ m2,
                            const float* __restrict__ v2,
                            const float* __restrict__ w3, const float* __restrict__ g3,
                            const float* __restrict__ b3, const float* __restrict__ m3,
                            const float* __restrict__ v3) {
    const int t = blockIdx.x * blockDim.x + threadIdx.x;
    const int stride = gridDim.x * blockDim.x;
    if (t == 0) g_ticket = 0;
    for (int i = t; i < C_ * C_; i += stride) {
        int o = i >> 6, c = i & 63;
        float sc = g1[o] * rsqrtf(v1[o] + EPS_);
        g_w1t[c * C_ + o] = w1[o * C_ + c] * sc;
    }
    for (int i = t; i < D_ * C_; i += stride) {
        int o = i >> 6;
        float sc2 = g2[o] * rsqrtf(v2[o] + EPS_);
        float wv2 = w2[i] * sc2;
        __nv_bfloat16 h2 = __float2bfloat16(wv2);
        g_w2hi[i] = h2;
        g_w2lo[i] = __float2bfloat16(wv2 - __bfloat162float(h2));
        float sc3 = g3[o] * rsqrtf(v3[o] + EPS_);
        float wv3 = w3[i] * sc3;
        __nv_bfloat16 h3 = __float2bfloat16(wv3);
        g_w3hi[i] = h3;
        g_w3lo[i] = __float2bfloat16(wv3 - __bfloat162float(h3));
    }
    if (t < C_) {
        float sc = g1[t] * rsqrtf(v1[t] + EPS_);
        g_sh1[t] = b1[t] - m1[t] * sc;
    }
    if (t < D_) {
        float sc2 = g2[t] * rsqrtf(v2[t] + EPS_);
        g_sh2[t] = b2[t] - m2[t] * sc2;
        float sc3 = g3[t] * rsqrtf(v3[t] + EPS_);
        g_sh3[t] = b3[t] - m3[t] * sc3;
    }
}

// ---------------- K1: p = relu(BN1(w1 @ f)), fp32 compute, fp16 store ----------------
__global__ __launch_bounds__(256, 2) void k1_kernel(const float* __restrict__ f) {
    extern __shared__ float sm1[];
    float* fsm = sm1;                // [64][256]
    float* wsm = sm1 + 64 * 256;     // [64][64]
    float* sh  = wsm + 64 * 64;      // [64]
    const int tid = threadIdx.x;
    const int b = blockIdx.y;
    const int n0 = blockIdx.x * 256;
    const float* fb = f + (size_t)b * C_ * N_ + n0;

    #pragma unroll
    for (int i = tid; i < 64 * 64; i += 256) {
        int c = i >> 6, j4 = i & 63;
        ((float4*)(fsm + c * 256))[j4] = ((const float4*)(fb + (size_t)c * N_))[j4];
    }
    #pragma unroll
    for (int i = tid; i < 1024; i += 256)
        ((float4*)wsm)[i] = ((const float4*)g_w1t)[i];
    if (tid < 64) sh[tid] = g_sh1[tid];
    __syncthreads();

    const int jg = tid & 63, og = tid >> 6;
    const int j0 = jg * 4, o0 = og * 16;
    unsigned long long acc[4][8];
    #pragma unroll
    for (int l = 0; l < 4; ++l)
        #pragma unroll
        for (int m = 0; m < 8; ++m) acc[l][m] = 0ULL;

    #pragma unroll 4
    for (int c = 0; c < 64; ++c) {
        float4 fv = *(const float4*)(fsm + c * 256 + j0);
        unsigned long long fp[4];
        fp[0] = pk2(fv.x, fv.x); fp[1] = pk2(fv.y, fv.y);
        fp[2] = pk2(fv.z, fv.z); fp[3] = pk2(fv.w, fv.w);
        const ulonglong2* wp = (const ulonglong2*)(wsm + c * 64 + o0);
        ulonglong2 wA = wp[0], wB = wp[1], wC = wp[2], wD = wp[3];
        unsigned long long wv[8] = {wA.x, wA.y, wB.x, wB.y, wC.x, wC.y, wD.x, wD.y};
        #pragma unroll
        for (int l = 0; l < 4; ++l)
            #pragma unroll
            for (int m = 0; m < 8; ++m)
                acc[l][m] = ffma2(fp[l], wv[m], acc[l][m]);
    }

    __half* pb = g_p + ((size_t)b * N_ + n0) * 64;
    #pragma unroll
    for (int l = 0; l < 4; ++l) {
        float o[16];
        #pragma unroll
        for (int m = 0; m < 8; ++m) upk2(acc[l][m], o[2 * m], o[2 * m + 1]);
        __half2 hh[8];
        #pragma unroll
        for (int m = 0; m < 8; ++m)
            hh[m] = __floats2half2_rn(fmaxf(o[2 * m] + sh[o0 + 2 * m], 0.0f),
                                      fmaxf(o[2 * m + 1] + sh[o0 + 2 * m + 1], 0.0f));
        uint4* dv = (uint4*)(pb + (size_t)(j0 + l) * 64 + o0);
        dv[0] = ((uint4*)hh)[0];
        dv[1] = ((uint4*)hh)[1];
    }
}

// ---------------- K2: persistent HMMA kernel ----------------
// X tiles stored [pt][ch] bf16, 144B row pitch (conflict-free b32 frag loads).
// Weights [o][c] bf16, 144B pitch.
#define SW_ 144
#define W2HI_ 0
#define W2LO_ 18432
#define W3HI_ 36864
#define W3LO_ 55296
#define XHH_ 73728
#define XHL_ 110592
#define XFH_ 147456
#define XFL_ 184320
#define CTRL_ 221184
#define SMEM2_ 221216

__global__ __launch_bounds__(512, 1) void k2_kernel(const float* __restrict__ f,
                                                    const int* __restrict__ nidx,
                                                    float* __restrict__ out) {
    extern __shared__ __align__(16) char smem[];
    const int tid = threadIdx.x;
    const int wid = tid >> 5, lane = tid & 31;
    const int g = lane >> 2, q = lane & 3;
    const int mq = wid >> 2, ns = wid & 3;

    // stage split weights into padded smem (once)
    for (int i = tid; i < 1024; i += 512) {
        int o = i >> 3, p8 = i & 7;
        uint32_t dst = o * SW_ + p8 * 16;
        *(uint4*)(smem + W2HI_ + dst) = ((const uint4*)g_w2hi)[i];
        *(uint4*)(smem + W2LO_ + dst) = ((const uint4*)g_w2lo)[i];
        *(uint4*)(smem + W3HI_ + dst) = ((const uint4*)g_w3hi)[i];
        *(uint4*)(smem + W3LO_ + dst) = ((const uint4*)g_w3lo)[i];
    }
    // persistent BN shifts for this thread's output rows
    float sh2r[2][2], sh3r[2][2];
    #pragma unroll
    for (int mt = 0; mt < 2; ++mt) {
        int o = mq * 32 + mt * 16 + g;
        sh2r[mt][0] = g_sh2[o];     sh2r[mt][1] = g_sh2[o + 8];
        sh3r[mt][0] = g_sh3[o];     sh3r[mt][1] = g_sh3[o + 8];
    }
    int* ctrl = (int*)(smem + CTRL_);

    for (;;) {
        __syncthreads();   // protects X from previous iteration's MMA reads
        if (tid == 0) ctrl[0] = atomicAdd(&g_ticket, 1);
        __syncthreads();
        const int t = ctrl[0];
        if (t >= TILES_) break;
        const int b = t / (N_ / NT_);
        const int n0 = (t % (N_ / NT_)) * NT_;

        // --- transpose + split f tile -> XF hi/lo ---
        const float* fb = f + (size_t)b * C_ * N_ + n0;
        #pragma unroll
        for (int it = 0; it < 16; ++it) {
            int idx = it * 512 + tid;
            int j = idx & 255, c = (idx >> 8) * 2;
            float x0 = fb[(size_t)c * N_ + j];
            float x1 = fb[(size_t)(c + 1) * N_ + j];
            uint32_t hi, lo;
            split2(x0, x1, hi, lo);
            *(uint32_t*)(smem + XFH_ + j * SW_ + c * 2) = hi;
            *(uint32_t*)(smem + XFL_ + j * SW_ + c * 2) = lo;
        }

        // --- gather-sum p (fp16) -> fp32 -> split -> XH hi/lo ---
        {
            const int j = tid >> 1, h = tid & 1;
            const int4* ib = (const int4*)(nidx + ((size_t)b * N_ + n0 + j) * 16);
            float acc[32];
            #pragma unroll
            for (int i = 0; i < 32; ++i) acc[i] = 0.f;
            #pragma unroll
            for (int k4 = 0; k4 < 4; ++k4) {
                int4 id = ib[k4];
                int ids[4] = {id.x, id.y, id.z, id.w};
                #pragma unroll
                for (int kk = 0; kk < 4; ++kk) {
                    const uint4* row =
                        (const uint4*)(g_p + ((size_t)b * N_ + ids[kk]) * 64 + h * 32);
                    #pragma unroll
                    for (int r = 0; r < 4; ++r) {
                        uint4 v = row[r];
                        const __half2* hp = (const __half2*)&v;
                        #pragma unroll
                        for (int u = 0; u < 4; ++u) {
                            float2 fv = __half22float2(hp[u]);
                            acc[r * 8 + u * 2] += fv.x;
                            acc[r * 8 + u * 2 + 1] += fv.y;
                        }
                    }
                }
            }
            #pragma unroll
            for (int q8 = 0; q8 < 4; ++q8) {
                uint32_t vh[4], vl[4];
                #pragma unroll
                for (int u = 0; u < 4; ++u)
                    split2(acc[q8 * 8 + 2 * u], acc[q8 * 8 + 2 * u + 1], vh[u], vl[u]);
                uint32_t off = j * SW_ + h * 64 + q8 * 16;
                *(uint4*)(smem + XHH_ + off) = make_uint4(vh[0], vh[1], vh[2], vh[3]);
                *(uint4*)(smem + XHL_ + off) = make_uint4(vl[0], vl[1], vl[2], vl[3]);
            }
        }
        __syncthreads();

        // --- MMA: warp computes both GEMMs for rows [mq*32, +32), cols [ns*64, +64) ---
        const int obase = mq * 32;
        float* outb = out + (size_t)b * D_ * N_ + n0;
        for (int ch = 0; ch < 2; ++ch) {
            float accA[2][4][4], accB[2][4][4];
            #pragma unroll
            for (int mt = 0; mt < 2; ++mt)
                #pragma unroll
                for (int nt = 0; nt < 4; ++nt)
                    #pragma unroll
                    for (int e = 0; e < 4; ++e) { accA[mt][nt][e] = 0.f; accB[mt][nt][e] = 0.f; }

            for (int k = 0; k < 4; ++k) {
                const int koff = 32 * k + 4 * q;
                uint32_t A0[2][4], A1[2][4], B0[4][2], B1[4][2];

                // GEMM1: W2 (hi/lo) x H (hi/lo)
                #pragma unroll
                for (int mt = 0; mt < 2; ++mt) {
                    int rb = (obase + mt * 16 + g) * SW_ + koff;
                    A0[mt][0] = *(uint32_t*)(smem + W2HI_ + rb);
                    A0[mt][1] = *(uint32_t*)(smem + W2HI_ + rb + 8 * SW_);
                    A0[mt][2] = *(uint32_t*)(smem + W2HI_ + rb + 16);
                    A0[mt][3] = *(uint32_t*)(smem + W2HI_ + rb + 8 * SW_ + 16);
                    A1[mt][0] = *(uint32_t*)(smem + W2LO_ + rb);
                    A1[mt][1] = *(uint32_t*)(smem + W2LO_ + rb + 8 * SW_);
                    A1[mt][2] = *(uint32_t*)(smem + W2LO_ + rb + 16);
                    A1[mt][3] = *(uint32_t*)(smem + W2LO_ + rb + 8 * SW_ + 16);
                }
                #pragma unroll
                for (int nt = 0; nt < 4; ++nt) {
                    int pb = (ns * 64 + ch * 32 + nt * 8 + g) * SW_ + koff;
                    B0[nt][0] = *(uint32_t*)(smem + XHH_ + pb);
                    B0[nt][1] = *(uint32_t*)(smem + XHH_ + pb + 16);
                    B1[nt][0] = *(uint32_t*)(smem + XHL_ + pb);
                    B1[nt][1] = *(uint32_t*)(smem + XHL_ + pb + 16);
                }
                #pragma unroll
                for (int mt = 0; mt < 2; ++mt)
                    #pragma unroll
                    for (int nt = 0; nt < 4; ++nt) {
                        mma16816(accA[mt][nt], A0[mt], B0[nt]);
                        mma16816(accA[mt][nt], A1[mt], B0[nt]);
                        mma16816(accA[mt][nt], A0[mt], B1[nt]);
                    }

                // GEMM2: W3 (hi/lo) x F (hi/lo)
                #pragma unroll
                for (int mt = 0; mt < 2; ++mt) {
                    int rb = (obase + mt * 16 + g) * SW_ + koff;
                    A0[mt][0] = *(uint32_t*)(smem + W3HI_ + rb);
                    A0[mt][1] = *(uint32_t*)(smem + W3HI_ + rb + 8 * SW_);
                    A0[mt][2] = *(uint32_t*)(smem + W3HI_ + rb + 16);
                    A0[mt][3] = *(uint32_t*)(smem + W3HI_ + rb + 8 * SW_ + 16);
                    A1[mt][0] = *(uint32_t*)(smem + W3LO_ + rb);
                    A1[mt][1] = *(uint32_t*)(smem + W3LO_ + rb + 8 * SW_);
                    A1[mt][2] = *(uint32_t*)(smem + W3LO_ + rb + 16);
                    A1[mt][3] = *(uint32_t*)(smem + W3LO_ + rb + 8 * SW_ + 16);
                }
                #pragma unroll
                for (int nt = 0; nt < 4; ++nt) {
                    int pb = (ns * 64 + ch * 32 + nt * 8 + g) * SW_ + koff;
                    B0[nt][0] = *(uint32_t*)(smem + XFH_ + pb);
                    B0[nt][1] = *(uint32_t*)(smem + XFH_ + pb + 16);
                    B1[nt][0] = *(uint32_t*)(smem + XFL_ + pb);
                    B1[nt][1] = *(uint32_t*)(smem + XFL_ + pb + 16);
                }
                #pragma unroll
                for (int mt = 0; mt < 2; ++mt)
                    #pragma unroll
                    for (int nt = 0; nt < 4; ++nt) {
                        mma16816(accB[mt][nt], A0[mt], B0[nt]);
                        mma16816(accB[mt][nt], A1[mt], B0[nt]);
                        mma16816(accB[mt][nt], A0[mt], B1[nt]);
                    }
            }

            // --- epilogue: res = relu(h+sh2) + relu(s+sh3), direct gmem stores ---
            #pragma unroll
            for (int mt = 0; mt < 2; ++mt) {
                int o = obase + mt * 16 + g;
                #pragma unroll
                for (int nt = 0; nt < 4; ++nt) {
                    int col = ns * 64 + ch * 32 + nt * 8 + q * 2;
                    float2 v0, v1;
                    v0.x = fmaxf(accA[mt][nt][0] + sh2r[mt][0], 0.f) +
                           fmaxf(accB[mt][nt][0] + sh3r[mt][0], 0.f);
                    v0.y = fmaxf(accA[mt][nt][1] + sh2r[mt][0], 0.f) +
                           fmaxf(accB[mt][nt][1] + sh3r[mt][0], 0.f);
                    v1.x = fmaxf(accA[mt][nt][2] + sh2r[mt][1], 0.f) +
                           fmaxf(accB[mt][nt][2] + sh3r[mt][1], 0.f);
                    v1.y = fmaxf(accA[mt][nt][3] + sh2r[mt][1], 0.f) +
                           fmaxf(accB[mt][nt][3] + sh3r[mt][1], 0.f);
                    *(float2*)(outb + (size_t)o * N_ + col) = v0;
                    *(float2*)(outb + (size_t)(o + 8) * N_ + col) = v1;
                }
            }
        }
    }
}

extern "C" void kernel_launch(void* const* d_in, const int* in_sizes, int n_in,
                              void* d_out, int out_size) {
    const float* feature = (const float*)d_in[0];
    const int* nidx = (const int*)d_in[1];
    const float* w1 = (const float*)d_in[2];
    const float* g1 = (const float*)d_in[3];
    const float* b1 = (const float*)d_in[4];
    const float* m1 = (const float*)d_in[5];
    const float* v1 = (const float*)d_in[6];
    const float* w2 = (const float*)d_in[7];
    const float* g2 = (const float*)d_in[8];
    const float* b2 = (const float*)d_in[9];
    const float* m2 = (const float*)d_in[10];
    const float* v2 = (const float*)d_in[11];
    const float* w3 = (const float*)d_in[12];
    const float* g3 = (const float*)d_in[13];
    const float* b3 = (const float*)d_in[14];
    const float* m3 = (const float*)d_in[15];
    const float* v3 = (const float*)d_in[16];
    float* out = (float*)d_out;

    const int SM1 = (64 * 256 + 64 * 64 + 64) * 4;  // 82176
    cudaFuncSetAttribute(k1_kernel, cudaFuncAttributeMaxDynamicSharedMemorySize, SM1);
    cudaFuncSetAttribute(k2_kernel, cudaFuncAttributeMaxDynamicSharedMemorySize, SMEM2_);

    prep_kernel<<<32, 256>>>(w1, g1, b1, m1, v1, w2, g2, b2, m2, v2, w3, g3, b3, m3, v3);
    k1_kernel<<<dim3(N_ / 256, B_), 256, SM1>>>(feature);
    k2_kernel<<<152, 512, SMEM2_>>>(feature, nidx, out);
}